// round 6
// baseline (speedup 1.0000x reference)
#include <cuda_runtime.h>
#include <cuda_bf16.h>
#include <math.h>
#include <stdint.h>

// Problem constants (QwenGroupedQueryAttention_44100724195922)
#define BB   2
#define TT   2048
#define EE   2048
#define HH   16
#define DD   128
#define GG   4
#define NKVH 4
#define KVD  512
#define N1   3072
#define MM   4096

__device__ float g_qkv[(size_t)MM * N1];             // fp32
__device__ float g_k[(size_t)BB * NKVH * TT * DD];   // tf32 bits
__device__ float g_v[(size_t)BB * NKVH * TT * DD];   // tf32 bits
__device__ float g_y[(size_t)MM * EE];               // tf32 bits (attn out)
__device__ float g_xt[(size_t)MM * EE];              // x as tf32 bits
__device__ float g_wat[(size_t)N1 * EE];             // Wa^T [N1][E] tf32 bits
__device__ float g_wpt[(size_t)EE * EE];             // Wp^T [E][E] tf32 bits

__device__ __forceinline__ uint32_t f2tf32(float x) {
    uint32_t r;
    asm("cvt.rna.tf32.f32 %0, %1;" : "=r"(r) : "f"(x));
    return r;
}

__device__ __forceinline__ void mma_tf32(float c[4], const uint32_t a[4],
                                         uint32_t b0, uint32_t b1) {
    asm volatile(
        "mma.sync.aligned.m16n8k8.row.col.f32.tf32.tf32.f32 "
        "{%0,%1,%2,%3}, {%4,%5,%6,%7}, {%8,%9}, {%0,%1,%2,%3};"
        : "+f"(c[0]), "+f"(c[1]), "+f"(c[2]), "+f"(c[3])
        : "r"(a[0]), "r"(a[1]), "r"(a[2]), "r"(a[3]), "r"(b0), "r"(b1));
}

__device__ __forceinline__ void cp16(uint32_t dst, const void* src) {
    asm volatile("cp.async.cg.shared.global [%0], [%1], 16;"
                 :: "r"(dst), "l"(src));
}
__device__ __forceinline__ void ldsm_x4(uint32_t* r, uint32_t a) {
    asm volatile("ldmatrix.sync.aligned.m8n8.x4.shared.b16 {%0,%1,%2,%3}, [%4];"
                 : "=r"(r[0]), "=r"(r[1]), "=r"(r[2]), "=r"(r[3]) : "r"(a));
}

// ---------------------------------------------------------------------------
// Elementwise fp32 -> tf32 bits
// ---------------------------------------------------------------------------
__global__ __launch_bounds__(256)
void conv_tf32(const float* __restrict__ in, float* __restrict__ out, int n4) {
    int i = blockIdx.x * 256 + threadIdx.x;
    if (i >= n4) return;
    float4 v = ((const float4*)in)[i];
    uint4 t;
    t.x = f2tf32(v.x); t.y = f2tf32(v.y); t.z = f2tf32(v.z); t.w = f2tf32(v.w);
    ((uint4*)out)[i] = t;
}

// ---------------------------------------------------------------------------
// Transpose + tf32: W[K][N] -> Wt[N][K]
// ---------------------------------------------------------------------------
__global__ __launch_bounds__(256)
void transpose_tf32(const float* __restrict__ W, float* __restrict__ Wt,
                    int K, int N) {
    __shared__ float tile[32][33];
    int n0 = blockIdx.x * 32, k0 = blockIdx.y * 32;
    int tx = threadIdx.x, ty = threadIdx.y;  // (32, 8)
#pragma unroll
    for (int j = 0; j < 4; j++)
        tile[ty + j * 8][tx] = W[(size_t)(k0 + ty + j * 8) * N + n0 + tx];
    __syncthreads();
#pragma unroll
    for (int j = 0; j < 4; j++)
        Wt[(size_t)(n0 + ty + j * 8) * K + k0 + tx] =
            __uint_as_float(f2tf32(tile[tx][ty + j * 8]));
}

// ---------------------------------------------------------------------------
// TF32 GEMM v3: C[M,N] = A[M,K] @ Bt[N,K]^T (+bias)
// Block tile 128x256, warps 2x4 (warp tile 64x64), BK=32, 3-stage cp.async,
// ldmatrix.x4 for both operands, XOR-swizzled smem.
// ---------------------------------------------------------------------------
#define STAGES 3
#define A_BYTES 16384            // 128 * 32 * 4
#define B_BYTES 32768            // 256 * 32 * 4
#define STG_TOT (A_BYTES + B_BYTES)
#define G_SMEM (STAGES * STG_TOT + 1024)

__global__ __launch_bounds__(256, 1)
void gemm_v3(const float* __restrict__ A, const float* __restrict__ Bt,
             const float* __restrict__ bias, float* __restrict__ C,
             int M, int N, int K) {
    extern __shared__ __align__(16) char smraw[];
    uint32_t base = (uint32_t)__cvta_generic_to_shared(smraw);
    base = (base + 1023) & ~1023u;

    const int tid = threadIdx.x;
    const int lane = tid & 31;
    const int wid = tid >> 5;
    const int wm = wid >> 2;   // 0..1  (m offset 64*wm)
    const int wn = wid & 3;    // 0..3  (n offset 64*wn)
    const int bm = blockIdx.y * 128, bn = blockIdx.x * 256;

    float acc[4][8][4];
#pragma unroll
    for (int mi = 0; mi < 4; mi++)
#pragma unroll
        for (int nj = 0; nj < 8; nj++)
#pragma unroll
            for (int r = 0; r < 4; r++) acc[mi][nj][r] = 0.f;

    const int srow = tid >> 3;   // 0..31
    const int sk4 = tid & 7;     // 0..7

    auto stage_fn = [&](int kt, int stg) {
        uint32_t sa = base + stg * STG_TOT;
        uint32_t sb = sa + A_BYTES;
        const float* ap = A + (size_t)bm * K + kt * 32 + sk4 * 4;
        const float* bp = Bt + (size_t)bn * K + kt * 32 + sk4 * 4;
#pragma unroll
        for (int i = 0; i < 4; i++) {
            int row = srow + i * 32;
            cp16(sa + row * 128 + ((sk4 ^ (row & 7)) << 4), ap + (size_t)row * K);
        }
#pragma unroll
        for (int i = 0; i < 8; i++) {
            int row = srow + i * 32;
            cp16(sb + row * 128 + ((sk4 ^ (row & 7)) << 4), bp + (size_t)row * K);
        }
        asm volatile("cp.async.commit_group;");
    };

    const int nkt = K / 32;
    stage_fn(0, 0);
    stage_fn(1, 1);

    const int mLane = wm * 64 + (lane & 15);  // + mi*16
    const int nLane = wn * 64 + (lane & 15);  // + bi*16
    const int k4hi = lane >> 4;               // + s*2

    for (int kt = 0; kt < nkt; kt++) {
        int cur = kt % STAGES;
        asm volatile("cp.async.wait_group 1;");
        __syncthreads();
        if (kt + 2 < nkt) stage_fn(kt + 2, (kt + 2) % STAGES);

        uint32_t aBase = base + cur * STG_TOT;
        uint32_t bBase = aBase + A_BYTES;
#pragma unroll
        for (int s = 0; s < 4; s++) {
            int k4 = s * 2 + k4hi;
            uint32_t af[4][4];
#pragma unroll
            for (int mi = 0; mi < 4; mi++) {
                int m = mLane + mi * 16;
                ldsm_x4(af[mi], aBase + ((m * 8 + (k4 ^ (m & 7))) << 4));
            }
            uint32_t bf[4][4];
#pragma unroll
            for (int bi = 0; bi < 4; bi++) {
                int n = nLane + bi * 16;
                ldsm_x4(bf[bi], bBase + ((n * 8 + (k4 ^ (n & 7))) << 4));
            }
#pragma unroll
            for (int mi = 0; mi < 4; mi++)
#pragma unroll
                for (int bi = 0; bi < 4; bi++) {
                    mma_tf32(acc[mi][bi * 2 + 0], af[mi], bf[bi][0], bf[bi][2]);
                    mma_tf32(acc[mi][bi * 2 + 1], af[mi], bf[bi][1], bf[bi][3]);
                }
        }
        __syncthreads();
    }

    const int g4 = lane >> 2, a4 = lane & 3;
#pragma unroll
    for (int mi = 0; mi < 4; mi++) {
        int row = bm + wm * 64 + mi * 16 + g4;
#pragma unroll
        for (int nj = 0; nj < 8; nj++) {
            int col = bn + wn * 64 + (nj >> 1) * 16 + (nj & 1) * 8 + 2 * a4;
            float bx = 0.f, by = 0.f;
            if (bias) { bx = bias[col]; by = bias[col + 1]; }
            *(float2*)(C + (size_t)row * N + col) =
                make_float2(acc[mi][nj][0] + bx, acc[mi][nj][1] + by);
            *(float2*)(C + (size_t)(row + 8) * N + col) =
                make_float2(acc[mi][nj][2] + bx, acc[mi][nj][3] + by);
        }
    }
}

// ---------------------------------------------------------------------------
// RoPE on K and V, split into [B,NKV,T,D], stored as TF32 bits.
// ---------------------------------------------------------------------------
__global__ __launch_bounds__(64)
void rope_split_kernel(const float* __restrict__ qkv,
                       const float* __restrict__ fc,
                       const float* __restrict__ fs,
                       float* __restrict__ Kg, float* __restrict__ Vg) {
    int t = blockIdx.x;
    int bk = blockIdx.y;
    int b = bk / NKVH, kv = bk % NKVH;
    int i = threadIdx.x;

    float c = fc[t * 64 + i];
    float s = fs[t * 64 + i];
    const float* row = qkv + ((size_t)(b * TT + t)) * N1;

    float k0 = row[EE + kv * DD + 2 * i];
    float k1 = row[EE + kv * DD + 2 * i + 1];
    float v0 = row[EE + KVD + kv * DD + 2 * i];
    float v1 = row[EE + KVD + kv * DD + 2 * i + 1];

    size_t o = ((size_t)(b * NKVH + kv) * TT + t) * DD + 2 * i;
    Kg[o]     = __uint_as_float(f2tf32(k0 * c - k1 * s));
    Kg[o + 1] = __uint_as_float(f2tf32(k0 * s + k1 * c));
    Vg[o]     = __uint_as_float(f2tf32(v0 * c - v1 * s));
    Vg[o + 1] = __uint_as_float(f2tf32(v0 * s + v1 * c));
}

// ---------------------------------------------------------------------------
// TF32 tensor-core flash attention, output stored as tf32 bits.
// ---------------------------------------------------------------------------
__device__ __forceinline__ void mma_tf32v(float c[4], const uint32_t a[4],
                                          const uint32_t b[2]) {
    mma_tf32(c, a, b[0], b[1]);
}

#define QS_S 132
#define KS_S 132
#define VS_S2 136
#define PS_S 68
#define SM_Q  0
#define SM_K  (128 * QS_S)
#define SM_V  (SM_K + 64 * KS_S)
#define SM_P  (SM_V + 64 * VS_S2)
#define SM_TOT (SM_P + 128 * PS_S)

__global__ __launch_bounds__(256, 1)
void attn_tf32(const float* __restrict__ qkv,
               const float* __restrict__ Kg,
               const float* __restrict__ Vg,
               float* __restrict__ Y) {
    extern __shared__ __align__(16) uint32_t smu[];
    uint32_t* Qs = smu + SM_Q;
    uint32_t* Ks = smu + SM_K;
    uint32_t* Vs = smu + SM_V;
    uint32_t* Ps = smu + SM_P;

    const int tid = threadIdx.x;
    const int lane = tid & 31;
    const int warp = tid >> 5;
    const int g4 = lane >> 2;
    const int a4 = lane & 3;

    const int qtile = (gridDim.x - 1) - blockIdx.x;
    const int bh = blockIdx.y;
    const int b = bh >> 4, h = bh & 15;
    const int kv = h >> 2;

    const float* qbase = qkv + ((size_t)(b * TT + qtile * 128)) * N1 + h * DD;
#pragma unroll
    for (int i = 0; i < 16; i++) {
        int idx = tid + i * 256;
        int row = idx >> 5;
        int col = (idx & 31) * 4;
        float4 q = *(const float4*)(qbase + (size_t)row * N1 + col);
        uint4 t;
        t.x = f2tf32(q.x); t.y = f2tf32(q.y);
        t.z = f2tf32(q.z); t.w = f2tf32(q.w);
        *(uint4*)(Qs + row * QS_S + col) = t;
    }

    float oacc[16][4];
#pragma unroll
    for (int nt = 0; nt < 16; nt++)
#pragma unroll
        for (int r = 0; r < 4; r++) oacc[nt][r] = 0.f;
    float m0 = -1e30f, m1 = -1e30f, l0 = 0.f, l1 = 0.f;

    const float scale = 0.08838834764831845f;
    const float* kbase = Kg + ((size_t)(b * NKVH + kv) * TT) * DD;
    const float* vbase = Vg + ((size_t)(b * NKVH + kv) * TT) * DD;

    const int rloc = warp * 16 + g4;
    const int grow0 = qtile * 128 + rloc;
    const int grow1 = grow0 + 8;

    const int njt = 2 * qtile + 2;
    for (int jt = 0; jt < njt; jt++) {
        __syncthreads();
#pragma unroll
        for (int i = 0; i < 8; i++) {
            int idx = tid + i * 256;
            int tok = idx >> 5;
            int col = (idx & 31) * 4;
            const float4* kp = (const float4*)(kbase + (size_t)(jt * 64 + tok) * DD + col);
            const float4* vp = (const float4*)(vbase + (size_t)(jt * 64 + tok) * DD + col);
            *(uint4*)(Ks + tok * KS_S + col) = *(const uint4*)kp;
            *(uint4*)(Vs + tok * VS_S2 + col) = *(const uint4*)vp;
        }
        __syncthreads();

        float sacc[8][4];
#pragma unroll
        for (int nt = 0; nt < 8; nt++)
#pragma unroll
            for (int r = 0; r < 4; r++) sacc[nt][r] = 0.f;

#pragma unroll
        for (int kt = 0; kt < 16; kt++) {
            uint32_t af[4];
            int c = kt * 8 + a4;
            af[0] = Qs[rloc * QS_S + c];
            af[1] = Qs[(rloc + 8) * QS_S + c];
            af[2] = Qs[rloc * QS_S + c + 4];
            af[3] = Qs[(rloc + 8) * QS_S + c + 4];
#pragma unroll
            for (int nt = 0; nt < 8; nt++) {
                uint32_t bf[2];
                int n = nt * 8 + g4;
                bf[0] = Ks[n * KS_S + kt * 8 + a4];
                bf[1] = Ks[n * KS_S + kt * 8 + a4 + 4];
                mma_tf32v(sacc[nt], af, bf);
            }
        }

        if (jt >= 2 * qtile) {
#pragma unroll
            for (int nt = 0; nt < 8; nt++) {
                int gc = jt * 64 + nt * 8 + 2 * a4;
                sacc[nt][0] = (gc     > grow0) ? -1e30f : sacc[nt][0] * scale;
                sacc[nt][1] = (gc + 1 > grow0) ? -1e30f : sacc[nt][1] * scale;
                sacc[nt][2] = (gc     > grow1) ? -1e30f : sacc[nt][2] * scale;
                sacc[nt][3] = (gc + 1 > grow1) ? -1e30f : sacc[nt][3] * scale;
            }
        } else {
#pragma unroll
            for (int nt = 0; nt < 8; nt++)
#pragma unroll
                for (int r = 0; r < 4; r++) sacc[nt][r] *= scale;
        }

        float rm0 = -1e30f, rm1 = -1e30f;
#pragma unroll
        for (int nt = 0; nt < 8; nt++) {
            rm0 = fmaxf(rm0, fmaxf(sacc[nt][0], sacc[nt][1]));
            rm1 = fmaxf(rm1, fmaxf(sacc[nt][2], sacc[nt][3]));
        }
        rm0 = fmaxf(rm0, __shfl_xor_sync(0xffffffffu, rm0, 1));
        rm0 = fmaxf(rm0, __shfl_xor_sync(0xffffffffu, rm0, 2));
        rm1 = fmaxf(rm1, __shfl_xor_sync(0xffffffffu, rm1, 1));
        rm1 = fmaxf(rm1, __shfl_xor_sync(0xffffffffu, rm1, 2));

        float mn0 = fmaxf(m0, rm0), mn1 = fmaxf(m1, rm1);
        float corr0 = __expf(m0 - mn0), corr1 = __expf(m1 - mn1);
        m0 = mn0; m1 = mn1;

        float rs0 = 0.f, rs1 = 0.f;
#pragma unroll
        for (int nt = 0; nt < 8; nt++) {
            float p0 = __expf(sacc[nt][0] - mn0);
            float p1 = __expf(sacc[nt][1] - mn0);
            float p2 = __expf(sacc[nt][2] - mn1);
            float p3 = __expf(sacc[nt][3] - mn1);
            rs0 += p0 + p1; rs1 += p2 + p3;
            int cc = nt * 8 + 2 * a4;
            *(uint2*)(Ps + rloc * PS_S + cc) = make_uint2(f2tf32(p0), f2tf32(p1));
            *(uint2*)(Ps + (rloc + 8) * PS_S + cc) = make_uint2(f2tf32(p2), f2tf32(p3));
        }
        rs0 += __shfl_xor_sync(0xffffffffu, rs0, 1);
        rs0 += __shfl_xor_sync(0xffffffffu, rs0, 2);
        rs1 += __shfl_xor_sync(0xffffffffu, rs1, 1);
        rs1 += __shfl_xor_sync(0xffffffffu, rs1, 2);
        l0 = l0 * corr0 + rs0;
        l1 = l1 * corr1 + rs1;

#pragma unroll
        for (int nt = 0; nt < 16; nt++) {
            oacc[nt][0] *= corr0; oacc[nt][1] *= corr0;
            oacc[nt][2] *= corr1; oacc[nt][3] *= corr1;
        }
        __syncwarp();

#pragma unroll
        for (int kt = 0; kt < 8; kt++) {
            uint32_t af[4];
            int c = kt * 8 + a4;
            af[0] = Ps[rloc * PS_S + c];
            af[1] = Ps[(rloc + 8) * PS_S + c];
            af[2] = Ps[rloc * PS_S + c + 4];
            af[3] = Ps[(rloc + 8) * PS_S + c + 4];
#pragma unroll
            for (int nt = 0; nt < 16; nt++) {
                uint32_t bf[2];
                bf[0] = Vs[(kt * 8 + a4) * VS_S2 + nt * 8 + g4];
                bf[1] = Vs[(kt * 8 + a4 + 4) * VS_S2 + nt * 8 + g4];
                mma_tf32v(oacc[nt], af, bf);
            }
        }
    }

    float inv0 = 1.f / l0, inv1 = 1.f / l1;
    int t0 = qtile * 128 + rloc;
    float* y0 = Y + ((size_t)(b * TT + t0)) * EE + h * DD;
    float* y1 = Y + ((size_t)(b * TT + t0 + 8)) * EE + h * DD;
#pragma unroll
    for (int nt = 0; nt < 16; nt++) {
        int cc = nt * 8 + 2 * a4;
        *(float2*)(y0 + cc) = make_float2(
            __uint_as_float(f2tf32(oacc[nt][0] * inv0)),
            __uint_as_float(f2tf32(oacc[nt][1] * inv0)));
        *(float2*)(y1 + cc) = make_float2(
            __uint_as_float(f2tf32(oacc[nt][2] * inv1)),
            __uint_as_float(f2tf32(oacc[nt][3] * inv1)));
    }
}

// ---------------------------------------------------------------------------
extern "C" void kernel_launch(void* const* d_in, const int* in_sizes, int n_in,
                              void* d_out, int out_size) {
    const float* x  = (const float*)d_in[0];
    const float* Wa = (const float*)d_in[1];
    const float* ba = (const float*)d_in[2];
    const float* Wp = (const float*)d_in[3];
    const float* fc = (const float*)d_in[4];
    const float* fs = (const float*)d_in[5];
    float* out = (float*)d_out;

    float *qkv, *kg, *vg, *yb, *xt, *wat, *wpt;
    cudaGetSymbolAddress((void**)&qkv, g_qkv);
    cudaGetSymbolAddress((void**)&kg, g_k);
    cudaGetSymbolAddress((void**)&vg, g_v);
    cudaGetSymbolAddress((void**)&yb, g_y);
    cudaGetSymbolAddress((void**)&xt, g_xt);
    cudaGetSymbolAddress((void**)&wat, g_wat);
    cudaGetSymbolAddress((void**)&wpt, g_wpt);

    // operand prep
    conv_tf32<<<(MM * EE / 4 + 255) / 256, 256>>>(x, xt, MM * EE / 4);
    transpose_tf32<<<dim3(N1 / 32, EE / 32), dim3(32, 8)>>>(Wa, wat, EE, N1);
    transpose_tf32<<<dim3(EE / 32, EE / 32), dim3(32, 8)>>>(Wp, wpt, EE, EE);

    cudaFuncSetAttribute(gemm_v3, cudaFuncAttributeMaxDynamicSharedMemorySize,
                         G_SMEM);

    // 1) QKV GEMM (+bias)
    gemm_v3<<<dim3(N1 / 256, MM / 128), 256, G_SMEM>>>(xt, wat, ba, qkv,
                                                       MM, N1, EE);

    // 2) RoPE on K and V
    rope_split_kernel<<<dim3(TT, BB * NKVH), 64>>>(qkv, fc, fs, kg, vg);

    // 3) attention
    int smem_bytes = SM_TOT * (int)sizeof(uint32_t);
    cudaFuncSetAttribute(attn_tf32, cudaFuncAttributeMaxDynamicSharedMemorySize,
                         smem_bytes);
    attn_tf32<<<dim3(TT / 128, BB * HH), 256, smem_bytes>>>(qkv, kg, vg, yb);

    // 4) output projection
    gemm_v3<<<dim3(EE / 256, MM / 128), 256, G_SMEM>>>(yb, wpt, nullptr, out,
                                                       MM, EE, EE);
}